// round 3
// baseline (speedup 1.0000x reference)
#include <cuda_runtime.h>
#include <math.h>

#define N_  256
#define T_  128
#define I_  512
#define H_  512
#define G_  2048            // 4*H
#define M_  (N_*T_)         // 32768
#define NTH (N_*T_*H_)      // 16777216

// ---------------- scratch (device globals: no allocation allowed) -----------
__device__ float g_gx[(size_t)T_ * N_ * G_];   // [t][n][4H]  (256 MB)
__device__ float g_gates[N_ * G_];             // per-step gates (2 MB)
__device__ float g_h[N_ * H_];
__device__ float g_c[N_ * H_];
__device__ float g_hs[(size_t)M_ * H_];        // [n][t][H]   (64 MB)

// ---------------- shared 128x128 fp32 GEMM tile (C = A * B^T), lda=ldb=512 --
__device__ __forceinline__ void gemm128(const float* __restrict__ A,
                                        const float* __restrict__ B,
                                        int K0, int K1, float acc[8][8])
{
    __shared__ float As[8][132];
    __shared__ float Bs[8][132];
    const int tid  = threadIdx.x;
    const int lrow = tid >> 1;          // 0..127
    const int lcol = (tid & 1) << 2;    // 0 or 4
    const int ty   = tid >> 4;          // 0..15
    const int tx   = tid & 15;          // 0..15
    const float* Ap = A + lrow * 512 + lcol;
    const float* Bp = B + lrow * 512 + lcol;

    for (int k = K0; k < K1; k += 8) {
        float4 av = *(const float4*)(Ap + k);
        float4 bv = *(const float4*)(Bp + k);
        __syncthreads();
        As[lcol+0][lrow]=av.x; As[lcol+1][lrow]=av.y;
        As[lcol+2][lrow]=av.z; As[lcol+3][lrow]=av.w;
        Bs[lcol+0][lrow]=bv.x; Bs[lcol+1][lrow]=bv.y;
        Bs[lcol+2][lrow]=bv.z; Bs[lcol+3][lrow]=bv.w;
        __syncthreads();
        #pragma unroll
        for (int kk = 0; kk < 8; kk++) {
            float4 a0 = *(const float4*)&As[kk][ty*8];
            float4 a1 = *(const float4*)&As[kk][ty*8+4];
            float4 b0 = *(const float4*)&Bs[kk][tx*8];
            float4 b1 = *(const float4*)&Bs[kk][tx*8+4];
            float ar[8] = {a0.x,a0.y,a0.z,a0.w,a1.x,a1.y,a1.z,a1.w};
            float br[8] = {b0.x,b0.y,b0.z,b0.w,b1.x,b1.y,b1.z,b1.w};
            #pragma unroll
            for (int i=0;i<8;i++)
                #pragma unroll
                for (int j=0;j<8;j++)
                    acc[i][j] = fmaf(ar[i], br[j], acc[i][j]);
        }
    }
}

// ---------------- kernels ---------------------------------------------------
__global__ void init_kernel(const float* __restrict__ hx, const float* __restrict__ cx)
{
    int idx = blockIdx.x * 256 + threadIdx.x;     // N*H
    int n = idx >> 9, k = idx & 511;
    g_h[idx] = hx[(size_t)n * T_ * H_ + k];       // hx[:,0,:]
    g_c[idx] = cx[(size_t)n * T_ * H_ + k];
}

// gx[t][n][g] = x[n,t,:] @ W_ih^T + b_ih + b_hh   (block bm == sample n)
__global__ void gemm_gx_kernel(const float* __restrict__ x,
                               const float* __restrict__ W_ih,
                               const float* __restrict__ b_ih,
                               const float* __restrict__ b_hh)
{
    float acc[8][8];
    #pragma unroll
    for (int i=0;i<8;i++)
        #pragma unroll
        for (int j=0;j<8;j++) acc[i][j]=0.f;

    const int bn = blockIdx.x, bm = blockIdx.y;
    gemm128(x + (size_t)bm*128*512, W_ih + (size_t)bn*128*512, 0, 512, acc);

    const int ty = threadIdx.x >> 4, tx = threadIdx.x & 15;
    const int col0 = bn*128 + tx*8;
    #pragma unroll
    for (int i=0;i<8;i++) {
        int t = ty*8 + i;                          // T_==128: local row == t
        float* dst = g_gx + ((size_t)t * N_ + bm) * G_ + col0;
        #pragma unroll
        for (int j=0;j<8;j++)
            dst[j] = acc[i][j] + b_ih[col0+j] + b_hh[col0+j];
    }
}

__global__ void copy_gx_kernel(int t)
{
    int v = blockIdx.x * 256 + threadIdx.x;        // N*G/4
    ((float4*)g_gates)[v] = ((const float4*)(g_gx + (size_t)t * N_ * G_))[v];
}

// gates[n,:] += r(n,t) * (h[n,:] @ W_hh^T), K-split over blockIdx.z
__global__ void gemm_step_kernel(const float* __restrict__ W_hh,
                                 const int* __restrict__ is_init, int t)
{
    float acc[8][8];
    #pragma unroll
    for (int i=0;i<8;i++)
        #pragma unroll
        for (int j=0;j<8;j++) acc[i][j]=0.f;

    const int bn = blockIdx.x, bm = blockIdx.y, kz = blockIdx.z;
    gemm128(g_h + (size_t)bm*128*512, W_hh + (size_t)bn*128*512,
            kz*128, kz*128 + 128, acc);

    const int ty = threadIdx.x >> 4, tx = threadIdx.x & 15;
    const int col0 = bn*128 + tx*8;
    #pragma unroll
    for (int i=0;i<8;i++) {
        int n = bm*128 + ty*8 + i;
        if (is_init[n*T_ + t] == 0) {              // r == 1
            float* dst = g_gates + (size_t)n * G_ + col0;
            #pragma unroll
            for (int j=0;j<8;j++) atomicAdd(dst + j, acc[i][j]);
        }                                          // r == 0: contribution is 0
    }
}

__device__ __forceinline__ float sigm(float x){ return 1.f / (1.f + expf(-x)); }

__global__ void pointwise_kernel(const int* __restrict__ is_init, int t)
{
    int idx = blockIdx.x * 256 + threadIdx.x;      // N*H
    int n = idx >> 9, k = idx & 511;
    float r = is_init[n*T_ + t] ? 0.f : 1.f;
    const float* g = g_gates + (size_t)n * G_;
    float ig = sigm(g[k]);
    float fg = sigm(g[H_ + k]);
    float gg = tanhf(g[2*H_ + k]);
    float og = sigm(g[3*H_ + k]);
    float cn = fg * (g_c[idx] * r) + ig * gg;
    float hn = og * tanhf(cn);
    g_c[idx] = cn;
    g_h[idx] = hn;
    g_hs[((size_t)n * T_ + t) * H_ + k] = hn;
}

// out[:NTH] = mish(hs @ W_out^T + b_out)
__global__ void gemm_out_kernel(const float* __restrict__ W_out,
                                const float* __restrict__ b_out,
                                float* __restrict__ out)
{
    float acc[8][8];
    #pragma unroll
    for (int i=0;i<8;i++)
        #pragma unroll
        for (int j=0;j<8;j++) acc[i][j]=0.f;

    const int bn = blockIdx.x, bm = blockIdx.y;
    gemm128(g_hs + (size_t)bm*128*512, W_out + (size_t)bn*128*512, 0, 512, acc);

    const int ty = threadIdx.x >> 4, tx = threadIdx.x & 15;
    const int col0 = bn*128 + tx*8;
    const int row0 = bm*128 + ty*8;
    #pragma unroll
    for (int i=0;i<8;i++) {
        #pragma unroll
        for (int j=0;j<8;j++) {
            float z  = acc[i][j] + b_out[col0+j];
            float sp = (z > 15.f) ? z : log1pf(expf(z));
            out[(size_t)(row0+i) * H_ + col0 + j] = z * tanhf(sp);
        }
    }
}

__global__ void replicate_kernel(float* __restrict__ out)
{
    int v = blockIdx.x * 256 + threadIdx.x;        // NTH/4
    int k4 = v & 127;
    int n  = v >> 14;                              // T*H/4 = 16384
    float4 hv = ((const float4*)g_h)[n*128 + k4];
    float4 cv = ((const float4*)g_c)[n*128 + k4];
    ((float4*)(out + NTH))[v]     = hv;
    ((float4*)(out + 2*(size_t)NTH))[v] = cv;
}

// ---------------- launcher ---------------------------------------------------
extern "C" void kernel_launch(void* const* d_in, const int* in_sizes, int n_in,
                              void* d_out, int out_size)
{
    const float* x     = (const float*)d_in[0];
    const int*   isi   = (const int*)  d_in[1];
    const float* hx    = (const float*)d_in[2];
    const float* cx    = (const float*)d_in[3];
    const float* W_ih  = (const float*)d_in[4];
    const float* W_hh  = (const float*)d_in[5];
    const float* b_ih  = (const float*)d_in[6];
    const float* b_hh  = (const float*)d_in[7];
    const float* W_out = (const float*)d_in[8];
    const float* b_out = (const float*)d_in[9];
    float* out = (float*)d_out;

    init_kernel<<<512, 256>>>(hx, cx);
    gemm_gx_kernel<<<dim3(16, 256), 256>>>(x, W_ih, b_ih, b_hh);

    for (int t = 0; t < T_; t++) {
        copy_gx_kernel<<<512, 256>>>(t);
        gemm_step_kernel<<<dim3(16, 2, 4), 256>>>(W_hh, isi, t);
        pointwise_kernel<<<512, 256>>>(isi, t);
    }

    gemm_out_kernel<<<dim3(4, 256), 256>>>(W_out, b_out, out);
    replicate_kernel<<<16384, 256>>>(out);
}

// round 5
// speedup vs baseline: 1.1453x; 1.1453x over previous
#include <cuda_runtime.h>
#include <math.h>

#define N_  256
#define T_  128
#define H_  512
#define G_  2048            // 4*H
#define M_  (N_*T_)         // 32768
#define NTH (N_*T_*H_)      // 16777216

typedef unsigned long long ull;

// ---------------- scratch (device globals: no allocation allowed) -----------
__device__ float g_gx[(size_t)T_ * N_ * G_];   // [t][n][packed 4H]
__device__ float g_h2[2][N_ * H_];             // double-buffered h
__device__ float g_c[N_ * H_];                 // final c
__device__ float g_hs[(size_t)M_ * H_];        // [n][t][H]
__device__ float g_biasp[G_];                  // packed b_ih+b_hh
__device__ unsigned g_count;
__device__ volatile unsigned g_gen;

// ---------------- f32x2 helpers ---------------------------------------------
__device__ __forceinline__ ull pk2(float lo, float hi){
    ull r; asm("mov.b64 %0, {%1,%2};" : "=l"(r) : "f"(lo), "f"(hi)); return r;
}
__device__ __forceinline__ void upk2(ull v, float& lo, float& hi){
    asm("mov.b64 {%0,%1}, %2;" : "=f"(lo), "=f"(hi) : "l"(v));
}
__device__ __forceinline__ void fma2(ull& d, ull a, ull b){
    asm("fma.rn.f32x2 %0, %1, %2, %0;" : "+l"(d) : "l"(a), "l"(b));
}
__device__ __forceinline__ float sigm(float x){ return 1.f/(1.f+expf(-x)); }

// ---------------- 128x128 fp32 GEMM tile (C = A * B^T), K=512, ld=512 -------
// acc2[i][jp] holds columns (tx*8+2jp, tx*8+2jp+1) for row ty*8+i.
// PERMB: B row index is bit-permuted so output columns are in packed order.
template<bool PERMB>
__device__ __forceinline__ void gemm128v2(const float* __restrict__ A,
                                          const float* __restrict__ B,
                                          int brow0, ull acc2[8][4])
{
    __shared__ float As[8][132];
    __shared__ float Bs[8][132];
    const int tid  = threadIdx.x;
    const int lrow = tid >> 1;
    const int lcol = (tid & 1) << 2;
    const int ty   = tid >> 4;
    const int tx   = tid & 15;
    int br = brow0 + lrow;
    if (PERMB) br = ((br & 3) << 9) | (br >> 2);
    const float* Ap = A + (size_t)lrow * 512 + lcol;
    const float* Bp = B + (size_t)br   * 512 + lcol;

    float4 av = *(const float4*)(Ap);
    float4 bv = *(const float4*)(Bp);
    for (int k = 0; k < 512; k += 8) {
        __syncthreads();
        As[lcol+0][lrow]=av.x; As[lcol+1][lrow]=av.y;
        As[lcol+2][lrow]=av.z; As[lcol+3][lrow]=av.w;
        Bs[lcol+0][lrow]=bv.x; Bs[lcol+1][lrow]=bv.y;
        Bs[lcol+2][lrow]=bv.z; Bs[lcol+3][lrow]=bv.w;
        __syncthreads();
        const int kn = (k + 8) & 511;                 // prefetch (wraps harmlessly)
        av = *(const float4*)(Ap + kn);
        bv = *(const float4*)(Bp + kn);
        #pragma unroll
        for (int kk = 0; kk < 8; kk++) {
            float4 b0 = *(const float4*)&Bs[kk][tx*8];
            float4 b1 = *(const float4*)&Bs[kk][tx*8+4];
            float4 a0 = *(const float4*)&As[kk][ty*8];
            float4 a1 = *(const float4*)&As[kk][ty*8+4];
            ull b2[4] = {pk2(b0.x,b0.y), pk2(b0.z,b0.w), pk2(b1.x,b1.y), pk2(b1.z,b1.w)};
            float ar[8] = {a0.x,a0.y,a0.z,a0.w,a1.x,a1.y,a1.z,a1.w};
            #pragma unroll
            for (int i = 0; i < 8; i++) {
                ull ad = pk2(ar[i], ar[i]);
                #pragma unroll
                for (int j = 0; j < 4; j++) fma2(acc2[i][j], ad, b2[j]);
            }
        }
    }
}

// ---------------- kernels ---------------------------------------------------
__global__ void init_kernel(const float* __restrict__ hx,
                            const float* __restrict__ b_ih,
                            const float* __restrict__ b_hh)
{
    int idx = blockIdx.x * 256 + threadIdx.x;     // N*H = 131072
    int n = idx >> 9, k = idx & 511;
    g_h2[0][idx] = hx[(size_t)n * T_ * H_ + k];   // hx[:,0,:]
    if (idx < G_) {
        int g = ((idx & 3) << 9) | (idx >> 2);
        g_biasp[idx] = b_ih[g] + b_hh[g];
    }
    if (idx == 0) { g_count = 0; g_gen = 0; }
}

// gx[t][n][pc] = x[n,t,:] @ W_ih^T (packed cols) + packed bias
__global__ void __launch_bounds__(256) gemm_gx_kernel(const float* __restrict__ x,
                                                      const float* __restrict__ W_ih)
{
    ull acc2[8][4];
    #pragma unroll
    for (int i=0;i<8;i++)
        #pragma unroll
        for (int j=0;j<4;j++) acc2[i][j]=0ull;

    const int bn = blockIdx.x, bm = blockIdx.y;   // bm = sample n; rows are t
    gemm128v2<true>(x + (size_t)bm*128*512, W_ih, bn*128, acc2);

    const int ty = threadIdx.x >> 4, tx = threadIdx.x & 15;
    const int col0 = bn*128 + tx*8;               // packed cols
    float4 bb0 = *(const float4*)&g_biasp[col0];
    float4 bb1 = *(const float4*)&g_biasp[col0+4];
    const float bias[8] = {bb0.x,bb0.y,bb0.z,bb0.w,bb1.x,bb1.y,bb1.z,bb1.w};
    #pragma unroll
    for (int i=0;i<8;i++) {
        int t = ty*8 + i;                          // local row == t (T_=128)
        float v[8];
        upk2(acc2[i][0],v[0],v[1]); upk2(acc2[i][1],v[2],v[3]);
        upk2(acc2[i][2],v[4],v[5]); upk2(acc2[i][3],v[6],v[7]);
        float* dst = g_gx + ((size_t)t * N_ + bm) * G_ + col0;
        #pragma unroll
        for (int j=0;j<8;j++) dst[j] = v[j] + bias[j];
    }
}

// ---------------- fused persistent recurrence -------------------------------
// grid = 128 CTAs x 128 threads (one wave -> co-resident -> grid sync is safe)
// CTA tile: 64 rows(n) x 64 packed cols; thread: 8 rows x 4 packed cols
// (= all 4 gates of ONE h-column) -> pointwise is thread-local, c lives in regs.
__device__ __forceinline__ void lstm_cell(float gi, float gf, float gg, float go,
                                          float r, float& c, float& h)
{
    float cn = sigm(gf) * (c * r) + sigm(gi) * tanhf(gg);
    h = sigm(go) * tanhf(cn);
    c = cn;
}

__global__ void __launch_bounds__(128,1) recurrence_kernel(
        const float* __restrict__ W_hh,
        const int*   __restrict__ is_init,
        const float* __restrict__ cx)
{
    __shared__ float As[16][72];
    __shared__ float Bs[16][72];
    __shared__ float rs[64];
    const int tid = threadIdx.x;
    const int bx  = blockIdx.x & 31;   // packed-col group (32)
    const int by  = blockIdx.x >> 5;   // row group (4)
    const int c0  = bx*64, n0 = by*64;
    const int ty  = tid >> 4, tx = tid & 15;
    const int hcol = (c0 + tx*4) >> 2;
    const int lrow = tid & 63;
    const int lk8  = (tid >> 6) * 8;   // 0 or 8
    const int cB   = c0 + lrow;        // packed col this loader owns
    const float* Bp = W_hh + (size_t)(((cB & 3) << 9) | (cB >> 2)) * 512 + lk8;

    float creg[8];
    #pragma unroll
    for (int i=0;i<8;i++)
        creg[i] = cx[(size_t)(n0+ty*8+i) * T_ * H_ + hcol];   // cx[:,0,:]

    for (int t = 0; t < T_; t++) {
        const float* hb = g_h2[t & 1];
        float* hnb      = g_h2[(t+1) & 1];
        if (tid < 64) rs[tid] = is_init[(n0+tid)*T_ + t] ? 0.f : 1.f;

        // prefetch gx tile for this thread (used in epilogue)
        float4 gxv[8];
        #pragma unroll
        for (int i=0;i<8;i++)
            gxv[i] = *(const float4*)&g_gx[((size_t)t*N_ + n0+ty*8+i)*G_ + c0 + tx*4];

        __syncthreads();                       // rs ready
        const float rv = rs[lrow];
        const float* Ap = hb + (size_t)(n0+lrow)*512 + lk8;

        ull acc2[4][4];
        #pragma unroll
        for (int i=0;i<4;i++)
            #pragma unroll
            for (int j=0;j<4;j++) acc2[i][j]=0ull;

        float4 a0 = *(const float4*)(Ap);
        float4 a1 = *(const float4*)(Ap+4);
        float4 b0 = *(const float4*)(Bp);
        float4 b1 = *(const float4*)(Bp+4);

        for (int k = 0; k < 512; k += 16) {
            __syncthreads();
            As[lk8+0][lrow]=a0.x*rv; As[lk8+1][lrow]=a0.y*rv;
            As[lk8+2][lrow]=a0.z*rv; As[lk8+3][lrow]=a0.w*rv;
            As[lk8+4][lrow]=a1.x*rv; As[lk8+5][lrow]=a1.y*rv;
            As[lk8+6][lrow]=a1.z*rv; As[lk8+7][lrow]=a1.w*rv;
            Bs[lk8+0][lrow]=b0.x; Bs[lk8+1][lrow]=b0.y;
            Bs[lk8+2][lrow]=b0.z; Bs[lk8+3][lrow]=b0.w;
            Bs[lk8+4][lrow]=b1.x; Bs[lk8+5][lrow]=b1.y;
            Bs[lk8+6][lrow]=b1.z; Bs[lk8+7][lrow]=b1.w;
            __syncthreads();
            const int kn = (k + 16) & 511;     // prefetch next chunk
            a0 = *(const float4*)(Ap+kn);  a1 = *(const float4*)(Ap+kn+4);
            b0 = *(const float4*)(Bp+kn);  b1 = *(const float4*)(Bp+kn+4);
            #pragma unroll
            for (int kk = 0; kk < 16; kk++) {
                float4 bf  = *(const float4*)&Bs[kk][tx*4];
                float4 af0 = *(const float4*)&As[kk][ty*8];
                float4 af1 = *(const float4*)&As[kk][ty*8+4];
                ull a2_0 = pk2(af0.x,af0.y), a2_1 = pk2(af0.z,af0.w);
                ull a2_2 = pk2(af1.x,af1.y), a2_3 = pk2(af1.z,af1.w);
                ull bb;
                bb = pk2(bf.x,bf.x);
                fma2(acc2[0][0],a2_0,bb); fma2(acc2[1][0],a2_1,bb);
                fma2(acc2[2][0],a2_2,bb); fma2(acc2[3][0],a2_3,bb);
                bb = pk2(bf.y,bf.y);
                fma2(acc2[0][1],a2_0,bb); fma2(acc2[1][1],a2_1,bb);
                fma2(acc2[2][1],a2_2,bb); fma2(acc2[3][1],a2_3,bb);
                bb = pk2(bf.z,bf.z);
                fma2(acc2[0][2],a2_0,bb); fma2(acc2[1][2],a2_1,bb);
                fma2(acc2[2][2],a2_2,bb); fma2(acc2[3][2],a2_3,bb);
                bb = pk2(bf.w,bf.w);
                fma2(acc2[0][3],a2_0,bb); fma2(acc2[1][3],a2_1,bb);
                fma2(acc2[2][3],a2_2,bb); fma2(acc2[3][3],a2_3,bb);
            }
        }

        // epilogue: acc2[p][j] holds rows (2p, 2p+1), gate j
        #pragma unroll
        for (int p = 0; p < 4; p++) {
            float i_lo,i_hi,f_lo,f_hi,g_lo,g_hi,o_lo,o_hi;
            upk2(acc2[p][0], i_lo, i_hi);
            upk2(acc2[p][1], f_lo, f_hi);
            upk2(acc2[p][2], g_lo, g_hi);
            upk2(acc2[p][3], o_lo, o_hi);
            {
                const int i = 2*p;
                const int n = n0 + ty*8 + i;
                float4 g4 = gxv[i];
                float hn;
                lstm_cell(i_lo+g4.x, f_lo+g4.y, g_lo+g4.z, o_lo+g4.w,
                          rs[ty*8+i], creg[i], hn);
                hnb[(size_t)n*H_ + hcol] = hn;
                g_hs[((size_t)n*T_ + t)*H_ + hcol] = hn;
            }
            {
                const int i = 2*p + 1;
                const int n = n0 + ty*8 + i;
                float4 g4 = gxv[i];
                float hn;
                lstm_cell(i_hi+g4.x, f_hi+g4.y, g_hi+g4.z, o_hi+g4.w,
                          rs[ty*8+i], creg[i], hn);
                hnb[(size_t)n*H_ + hcol] = hn;
                g_hs[((size_t)n*T_ + t)*H_ + hcol] = hn;
            }
        }

        // grid barrier (skip after last step)
        if (t != T_-1) {
            __threadfence();
            __syncthreads();
            if (tid == 0) {
                unsigned prev = atomicAdd(&g_count, 1u);
                if (prev == (unsigned)(gridDim.x - 1)) {
                    g_count = 0u;
                    __threadfence();
                    g_gen = (unsigned)(t + 1);
                } else {
                    while (g_gen != (unsigned)(t + 1)) __nanosleep(64);
                    __threadfence();
                }
            }
            __syncthreads();
        }
    }

    // final c
    #pragma unroll
    for (int i=0;i<8;i++)
        g_c[(size_t)(n0+ty*8+i)*H_ + hcol] = creg[i];
}

// out[:NTH] = mish(hs @ W_out^T + b_out)
__global__ void __launch_bounds__(256) gemm_out_kernel(const float* __restrict__ W_out,
                                                       const float* __restrict__ b_out,
                                                       float* __restrict__ out)
{
    ull acc2[8][4];
    #pragma unroll
    for (int i=0;i<8;i++)
        #pragma unroll
        for (int j=0;j<4;j++) acc2[i][j]=0ull;

    const int bn = blockIdx.x, bm = blockIdx.y;
    gemm128v2<false>(g_hs + (size_t)bm*128*512, W_out, bn*128, acc2);

    const int ty = threadIdx.x >> 4, tx = threadIdx.x & 15;
    const int col0 = bn*128 + tx*8;
    const int row0 = bm*128 + ty*8;
    #pragma unroll
    for (int i=0;i<8;i++) {
        float v[8];
        upk2(acc2[i][0],v[0],v[1]); upk2(acc2[i][1],v[2],v[3]);
        upk2(acc2[i][2],v[4],v[5]); upk2(acc2[i][3],v[6],v[7]);
        #pragma unroll
        for (int j=0;j<8;j++) {
            float z  = v[j] + b_out[col0+j];
            float sp = (z > 15.f) ? z : log1pf(expf(z));
            out[(size_t)(row0+i) * H_ + col0 + j] = z * tanhf(sp);
        }
    }
}

__global__ void replicate_kernel(float* __restrict__ out)
{
    int v = blockIdx.x * 256 + threadIdx.x;        // NTH/4
    int k4 = v & 127;
    int n  = v >> 14;                              // T*H/4 = 16384 per sample
    float4 hv = ((const float4*)g_h2[0])[n*128 + k4];   // T even -> final in buf 0
    float4 cv = ((const float4*)g_c)[n*128 + k4];
    ((float4*)(out + NTH))[v]           = hv;
    ((float4*)(out + 2*(size_t)NTH))[v] = cv;
}

// ---------------- launcher ---------------------------------------------------
extern "C" void kernel_launch(void* const* d_in, const int* in_sizes, int n_in,
                              void* d_out, int out_size)
{
    const float* x     = (const float*)d_in[0];
    const int*   isi   = (const int*)  d_in[1];
    const float* hx    = (const float*)d_in[2];
    const float* cx    = (const float*)d_in[3];
    const float* W_ih  = (const float*)d_in[4];
    const float* W_hh  = (const float*)d_in[5];
    const float* b_ih  = (const float*)d_in[6];
    const float* b_hh  = (const float*)d_in[7];
    const float* W_out = (const float*)d_in[8];
    const float* b_out = (const float*)d_in[9];
    float* out = (float*)d_out;

    init_kernel<<<512, 256>>>(hx, b_ih, b_hh);
    gemm_gx_kernel<<<dim3(16, 256), 256>>>(x, W_ih);
    recurrence_kernel<<<128, 128>>>(W_hh, isi, cx);
    gemm_out_kernel<<<dim3(4, 256), 256>>>(W_out, b_out, out);
    replicate_kernel<<<16384, 256>>>(out);
}